// round 11
// baseline (speedup 1.0000x reference)
#include <cuda_runtime.h>
#include <math.h>

// Problem dims (fixed for this dataset)
#define B_   64
#define T_   512
#define IN_  512
#define HID_ 1024
#define OUT_ 512
#define NBLK 128        // persistent blocks (<=148 SMs -> all co-resident)
#define KS_  16         // split-K slices (64 k each)
#define JT_  8          // j-tiles of 128

typedef unsigned long long ull;

// packed fp32x2 FMA helpers (bit-identical to scalar FFMA)
#define FMA2(d, a, b) asm("fma.rn.f32x2 %0, %1, %2, %0;" : "+l"(d) : "l"(a), "l"(b))
#define DUP2(d, s)    asm("mov.b64 %0, {%1, %1};" : "=l"(d) : "r"(__float_as_uint(s)))
#define UNPK2(lo, hi, s) asm("mov.b64 {%0, %1}, %2;" : "=f"(lo), "=f"(hi) : "l"(s))

// Scratch (allocation-free contract: __device__ globals; BSS zero-init)
__device__ float g_xp[(size_t)T_ * B_ * HID_];     // [t][b][j]
__device__ float g_hseq[(size_t)T_ * B_ * HID_];   // [t][b][j]
__device__ float g_hT[2][HID_ * B_];               // ping-pong transposed hidden [j][b]
__device__ float g_part[2][KS_][B_ * HID_];        // double-buffered split-K partials
__device__ unsigned g_flags[NBLK];                 // per-block arrival flags (monotonic)
__device__ unsigned g_phase;                       // release word (monotonic)

__device__ __forceinline__ float ldcg_f(const float* p) {
    float v; asm volatile("ld.global.cg.f32 %0, [%1];" : "=f"(v) : "l"(p)); return v;
}
__device__ __forceinline__ float4 ldcg_f4(const float* p) {
    float4 v;
    asm volatile("ld.global.cg.v4.f32 {%0,%1,%2,%3}, [%4];"
                 : "=f"(v.x), "=f"(v.y), "=f"(v.z), "=f"(v.w) : "l"(p));
    return v;
}
__device__ __forceinline__ void stcg_f4(float* p, float4 v) {
    asm volatile("st.global.cg.v4.f32 [%0], {%1,%2,%3,%4};"
                 :: "l"(p), "f"(v.x), "f"(v.y), "f"(v.z), "f"(v.w));
}
__device__ __forceinline__ unsigned ld_acq(const unsigned* p) {
    unsigned v; asm volatile("ld.acquire.gpu.u32 %0, [%1];" : "=r"(v) : "l"(p)); return v;
}
__device__ __forceinline__ void st_rel(unsigned* p, unsigned v) {
    asm volatile("st.release.gpu.u32 [%0], %1;" :: "l"(p), "r"(v));
}

// Flag-array grid barrier: no contended atomics. Block 0 collects all flags,
// bumps the phase word. Values are monotonic (base + ord) -> graph-replay-safe,
// nothing to reset. Acquire/release on the signal words.
__device__ __forceinline__ void grid_barrier(unsigned base, unsigned ord) {
    const unsigned tgt = base + ord;
    const int tid = threadIdx.x;
    __threadfence();       // publish this block's data writes
    __syncthreads();
    if (blockIdx.x == 0) {
        if (tid >= 1 && tid < NBLK) {
            while ((int)(ld_acq(&g_flags[tid]) - tgt) < 0) __nanosleep(32);
        }
        __syncthreads();
        if (tid == 0) st_rel(&g_phase, tgt);
    } else {
        if (tid == 0) {
            st_rel(&g_flags[blockIdx.x], tgt);
            while ((int)(ld_acq(&g_phase) - tgt) < 0) __nanosleep(32);
        }
        __syncthreads();
    }
    __threadfence();
}

// ---------------------------------------------------------------------------
// Big GEMM (both projections): C[m,n] = sum_k A[m,k]*Bm[n,k] + bias[n]
// 128x128 block tile, 512 threads, 8m x 4n per thread, f32x2, double-buffered.
// MODE 0: A = param (input), write g_xp with m=(b*T+t) -> [t][b][n]
// MODE 1: A = g_hseq (device symbol, resolved IN DEVICE CODE), write C with
//         m=(t*B+b) -> [b][t][n].
// ---------------------------------------------------------------------------
template<int KDIM, int MODE>
__global__ __launch_bounds__(512) void big_gemm(const float* __restrict__ A_param,
                                                const float* __restrict__ Bm,
                                                const float* __restrict__ bias,
                                                float* __restrict__ C) {
    // device-side resolution of the A operand (host code must NOT touch __device__ symbols)
    const float* __restrict__ A = (MODE == 1) ? g_hseq : A_param;

    __shared__ float sA[2][16][132];
    __shared__ float sB[2][16][132];
    const int m0 = blockIdx.y * 128;
    const int n0 = blockIdx.x * 128;
    const int tid = threadIdx.x;
    const int srow = tid >> 2;     // 0..127 staging row
    const int skq  = tid & 3;      // 0..3   staging k-quad
    const int tmr  = tid >> 5;     // 0..15  m-group (8 rows)
    const int tnr  = tid & 31;     // 0..31  n-group (4 cols)

    // prologue: load chunk 0 -> regs -> buf 0
    float4 ra = *reinterpret_cast<const float4*>(&A [(size_t)(m0 + srow) * KDIM + skq * 4]);
    float4 rb = *reinterpret_cast<const float4*>(&Bm[(size_t)(n0 + srow) * KDIM + skq * 4]);
    sA[0][skq * 4 + 0][srow] = ra.x; sA[0][skq * 4 + 1][srow] = ra.y;
    sA[0][skq * 4 + 2][srow] = ra.z; sA[0][skq * 4 + 3][srow] = ra.w;
    sB[0][skq * 4 + 0][srow] = rb.x; sB[0][skq * 4 + 1][srow] = rb.y;
    sB[0][skq * 4 + 2][srow] = rb.z; sB[0][skq * 4 + 3][srow] = rb.w;
    __syncthreads();

    ull acc[8][2] = {};
    const int NC = KDIM / 16;

    for (int c = 0; c < NC; c++) {
        if (c + 1 < NC) {
            ra = *reinterpret_cast<const float4*>(&A [(size_t)(m0 + srow) * KDIM + (c + 1) * 16 + skq * 4]);
            rb = *reinterpret_cast<const float4*>(&Bm[(size_t)(n0 + srow) * KDIM + (c + 1) * 16 + skq * 4]);
        }
        const int cb = c & 1;
        #pragma unroll
        for (int kk = 0; kk < 16; kk++) {
            float4 a0v = *reinterpret_cast<const float4*>(&sA[cb][kk][tmr * 8]);
            float4 a1v = *reinterpret_cast<const float4*>(&sA[cb][kk][tmr * 8 + 4]);
            ulonglong2 bv = *reinterpret_cast<const ulonglong2*>(&sB[cb][kk][tnr * 4]);
            ull a_[8];
            DUP2(a_[0], a0v.x); DUP2(a_[1], a0v.y); DUP2(a_[2], a0v.z); DUP2(a_[3], a0v.w);
            DUP2(a_[4], a1v.x); DUP2(a_[5], a1v.y); DUP2(a_[6], a1v.z); DUP2(a_[7], a1v.w);
            #pragma unroll
            for (int mi = 0; mi < 8; mi++) {
                FMA2(acc[mi][0], a_[mi], bv.x);
                FMA2(acc[mi][1], a_[mi], bv.y);
            }
        }
        if (c + 1 < NC) {
            const int nb = (c + 1) & 1;
            sA[nb][skq * 4 + 0][srow] = ra.x; sA[nb][skq * 4 + 1][srow] = ra.y;
            sA[nb][skq * 4 + 2][srow] = ra.z; sA[nb][skq * 4 + 3][srow] = ra.w;
            sB[nb][skq * 4 + 0][srow] = rb.x; sB[nb][skq * 4 + 1][srow] = rb.y;
            sB[nb][skq * 4 + 2][srow] = rb.z; sB[nb][skq * 4 + 3][srow] = rb.w;
        }
        __syncthreads();
    }

    const float4 bv4 = *reinterpret_cast<const float4*>(&bias[n0 + tnr * 4]);
    #pragma unroll
    for (int mi = 0; mi < 8; mi++) {
        const int m = m0 + tmr * 8 + mi;
        float4 v;
        UNPK2(v.x, v.y, acc[mi][0]);
        UNPK2(v.z, v.w, acc[mi][1]);
        v.x += bv4.x; v.y += bv4.y; v.z += bv4.z; v.w += bv4.w;
        if (MODE == 0) {
            const int bb = m >> 9;        // m / T_
            const int tt = m & (T_ - 1);
            *reinterpret_cast<float4*>(&g_xp[((size_t)tt * B_ + bb) * HID_ + n0 + tnr * 4]) = v;
        } else {
            const int tt = m >> 6;        // m / B_
            const int bb = m & (B_ - 1);
            *reinterpret_cast<float4*>(&C[((size_t)bb * T_ + tt) * OUT_ + n0 + tnr * 4]) = v;
        }
    }
}

// ---------------------------------------------------------------------------
// Persistent recurrence: ONE launch for all 512 steps.
// 128 blocks (jx 0..7: j-tile 128, ksi 0..15: k-slice 64), 512 threads.
// sW resident in SMEM (32KB) for the whole sequence. Per step:
//   stage shh slice (16KB, ldcg) -> sync-free GEMM -> partials (L2, ping-pong)
//   -> barrier -> disjoint reduce + tanh -> hT + hseq -> barrier.
// ---------------------------------------------------------------------------
__global__ __launch_bounds__(512, 1) void rnn_persistent(const float* __restrict__ Whh) {
    __shared__ float sW[64][128];   // [k][j] resident (32KB)
    __shared__ float sh[64][64];    // [k][b] per-step slice (16KB); sred overlays

    const int tid = threadIdx.x;
    const int bid = blockIdx.x;
    const int jx  = bid & (JT_ - 1);
    const int ksi = bid >> 3;
    const int j0  = jx * 128;
    const int k0  = ksi * 64;
    const int w    = tid >> 5;
    const int lane = tid & 31;
    // square warp footprint: 8 j-quads (128B) x 4 b-quads (64B) per warp
    const int tjq = (w & 3) * 8 + (lane & 7);    // 0..31 -> j = j0 + tjq*4
    const int tbq = (w >> 2) * 4 + (lane >> 3);  // 0..15 -> b = tbq*4
    // disjoint reduce region: 64 j x 8 b per block
    const int rj0 = (bid & 15) * 64;
    const int rb0 = (bid >> 4) * 8;
    const int rj = rj0 + (tid & 63);
    const int rb = rb0 + (tid >> 6);
    float* sred = &sh[0][0];        // overlay: 64 x 9 floats (sh dead during reduce)

    const unsigned base = ld_acq(&g_phase);
    unsigned ord = 0;

    // resident W tile: sW[k][j] <- Whh[j0+jj][k0+k]
    #pragma unroll
    for (int q = 0; q < 4; q++) {
        const int idx = q * 512 + tid;   // 2048 float4
        const int jj = idx >> 4;
        const int kq = idx & 15;
        float4 wv = *reinterpret_cast<const float4*>(&Whh[(size_t)(j0 + jj) * HID_ + k0 + kq * 4]);
        sW[kq * 4 + 0][jj] = wv.x; sW[kq * 4 + 1][jj] = wv.y;
        sW[kq * 4 + 2][jj] = wv.z; sW[kq * 4 + 3][jj] = wv.w;
    }

    // ---- step 0: h0 = tanh(xp[0]) over this block's disjoint region ----
    {
        const size_t off = (size_t)rb * HID_ + rj;
        const float v = tanhf(g_xp[off]);
        g_hseq[off] = v;
        sred[(tid & 63) * 9 + (tid >> 6)] = v;
        __syncthreads();
        const int jrow = tid >> 3, bcol = tid & 7;
        g_hT[0][(rj0 + jrow) * B_ + rb0 + bcol] = sred[jrow * 9 + bcol];
    }
    grid_barrier(base, ++ord);

    for (int t = 1; t < T_; t++) {
        const float* __restrict__ hTp = g_hT[(t - 1) & 1];

        // stage h slice: sh[k][b] <- hT[k0+k][b]
        #pragma unroll
        for (int q = 0; q < 2; q++) {
            const int idx = q * 512 + tid;   // 1024 float4
            const int k = idx >> 4;
            const int b4 = idx & 15;
            float4 hv = ldcg_f4(&hTp[(k0 + k) * B_ + b4 * 4]);
            *reinterpret_cast<float4*>(&sh[k][b4 * 4]) = hv;
        }
        __syncthreads();

        // sync-free GEMM over resident smem
        ull acc[2][4] = {};
        #pragma unroll 16
        for (int kk = 0; kk < 64; kk++) {
            ulonglong2 h2 = *reinterpret_cast<const ulonglong2*>(&sh[kk][tbq * 4]);
            float4 wv = *reinterpret_cast<const float4*>(&sW[kk][tjq * 4]);
            ull w0, w1, w2, w3;
            DUP2(w0, wv.x); DUP2(w1, wv.y); DUP2(w2, wv.z); DUP2(w3, wv.w);
            FMA2(acc[0][0], h2.x, w0); FMA2(acc[0][1], h2.x, w1);
            FMA2(acc[0][2], h2.x, w2); FMA2(acc[0][3], h2.x, w3);
            FMA2(acc[1][0], h2.y, w0); FMA2(acc[1][1], h2.y, w1);
            FMA2(acc[1][2], h2.y, w2); FMA2(acc[1][3], h2.y, w3);
        }

        // write partials (ping-pong buffer by t parity)
        {
            float* __restrict__ pdst = g_part[t & 1][ksi];
            float4 r0, r1, r2, r3;
            UNPK2(r0.x, r1.x, acc[0][0]); UNPK2(r0.y, r1.y, acc[0][1]);
            UNPK2(r0.z, r1.z, acc[0][2]); UNPK2(r0.w, r1.w, acc[0][3]);
            UNPK2(r2.x, r3.x, acc[1][0]); UNPK2(r2.y, r3.y, acc[1][1]);
            UNPK2(r2.z, r3.z, acc[1][2]); UNPK2(r2.w, r3.w, acc[1][3]);
            const size_t o = (size_t)(tbq * 4) * HID_ + j0 + tjq * 4;
            stcg_f4(&pdst[o],            r0);
            stcg_f4(&pdst[o + HID_],     r1);
            stcg_f4(&pdst[o + 2 * HID_], r2);
            stcg_f4(&pdst[o + 3 * HID_], r3);
        }

        grid_barrier(base, ++ord);   // all partials published

        // disjoint reduce + tanh; write hseq[t] and transposed hT[t&1]
        {
            const size_t off = (size_t)rb * HID_ + rj;
            float s = g_xp[(size_t)t * B_ * HID_ + off];
            #pragma unroll
            for (int ks = 0; ks < KS_; ks++)
                s += ldcg_f(&g_part[t & 1][ks][off]);
            const float v = tanhf(s);
            g_hseq[(size_t)t * B_ * HID_ + off] = v;
            sred[(tid & 63) * 9 + (tid >> 6)] = v;
            __syncthreads();
            const int jrow = tid >> 3, bcol = tid & 7;
            g_hT[t & 1][(rj0 + jrow) * B_ + rb0 + bcol] = sred[jrow * 9 + bcol];
        }

        grid_barrier(base, ++ord);   // hT[t] published
    }
}

// ---------------------------------------------------------------------------
extern "C" void kernel_launch(void* const* d_in, const int* in_sizes, int n_in,
                              void* d_out, int out_size) {
    const float* input = (const float*)d_in[0];
    const float* W_ih  = (const float*)d_in[1];
    const float* W_hh  = (const float*)d_in[2];
    const float* bias  = (const float*)d_in[3];
    const float* W_out = (const float*)d_in[4];
    const float* b_out = (const float*)d_in[5];
    float* out = (float*)d_out;

    // 1) input projection for all timesteps
    big_gemm<IN_, 0><<<dim3(HID_ / 128, (B_ * T_) / 128), 512>>>(input, W_ih, bias, nullptr);

    // 2) persistent recurrence: one kernel for all 512 steps
    rnn_persistent<<<NBLK, 512>>>(W_hh);

    // 3) output projection for all timesteps (A = g_hseq resolved in device code)
    big_gemm<HID_, 1><<<dim3(OUT_ / 128, (B_ * T_) / 128), 512>>>(nullptr, W_out, b_out, out);
}

// round 12
// speedup vs baseline: 1.0418x; 1.0418x over previous
#include <cuda_runtime.h>
#include <math.h>

// Problem dims (fixed for this dataset)
#define B_   64
#define T_   512
#define IN_  512
#define HID_ 1024
#define OUT_ 512
#define NBLK 128        // persistent blocks (<=148 SMs -> all co-resident)
#define KS_  16         // split-K slices (64 k each)
#define JT_  8          // j-tiles of 128

typedef unsigned long long ull;

// packed fp32x2 FMA helpers (bit-identical to scalar FFMA)
#define FMA2(d, a, b) asm("fma.rn.f32x2 %0, %1, %2, %0;" : "+l"(d) : "l"(a), "l"(b))
#define DUP2(d, s)    asm("mov.b64 %0, {%1, %1};" : "=l"(d) : "r"(__float_as_uint(s)))
#define UNPK2(lo, hi, s) asm("mov.b64 {%0, %1}, %2;" : "=f"(lo), "=f"(hi) : "l"(s))

// Scratch (allocation-free contract: __device__ globals; BSS zero-init)
__device__ float g_xp[(size_t)T_ * B_ * HID_];     // [t][b][j]
__device__ float g_hseq[(size_t)T_ * B_ * HID_];   // [t][b][j]
__device__ float g_hT[2][HID_ * B_];               // ping-pong transposed hidden [j][b]
__device__ float g_part[2][KS_][B_ * HID_];        // double-buffered split-K partials
__device__ unsigned g_flags[NBLK];                 // per-block arrival flags (monotonic)
__device__ unsigned g_phase;                       // release word (monotonic)

__device__ __forceinline__ float ldcg_f(const float* p) {
    float v; asm volatile("ld.global.cg.f32 %0, [%1];" : "=f"(v) : "l"(p)); return v;
}
__device__ __forceinline__ float4 ldcg_f4(const float* p) {
    float4 v;
    asm volatile("ld.global.cg.v4.f32 {%0,%1,%2,%3}, [%4];"
                 : "=f"(v.x), "=f"(v.y), "=f"(v.z), "=f"(v.w) : "l"(p));
    return v;
}
__device__ __forceinline__ void stcg_f4(float* p, float4 v) {
    asm volatile("st.global.cg.v4.f32 [%0], {%1,%2,%3,%4};"
                 :: "l"(p), "f"(v.x), "f"(v.y), "f"(v.z), "f"(v.w));
}
__device__ __forceinline__ unsigned ld_acq(const unsigned* p) {
    unsigned v; asm volatile("ld.acquire.gpu.u32 %0, [%1];" : "=r"(v) : "l"(p)); return v;
}
__device__ __forceinline__ void st_rel(unsigned* p, unsigned v) {
    asm volatile("st.release.gpu.u32 [%0], %1;" :: "l"(p), "r"(v));
}

// Flag-array grid barrier: no contended atomics. Block 0 collects all flags,
// bumps the phase word. Values are monotonic (base + ord) -> graph-replay-safe,
// nothing to reset. Acquire/release on the signal words.
__device__ __forceinline__ void grid_barrier(unsigned base, unsigned ord) {
    const unsigned tgt = base + ord;
    const int tid = threadIdx.x;
    __threadfence();       // publish this block's data writes
    __syncthreads();
    if (blockIdx.x == 0) {
        if (tid >= 1 && tid < NBLK) {
            while ((int)(ld_acq(&g_flags[tid]) - tgt) < 0) __nanosleep(32);
        }
        __syncthreads();
        if (tid == 0) st_rel(&g_phase, tgt);
    } else {
        if (tid == 0) {
            st_rel(&g_flags[blockIdx.x], tgt);
            while ((int)(ld_acq(&g_phase) - tgt) < 0) __nanosleep(32);
        }
        __syncthreads();
    }
    __threadfence();
}

// ---------------------------------------------------------------------------
// Big GEMM (both projections): C[m,n] = sum_k A[m,k]*Bm[n,k] + bias[n]
// 128x128 block tile, 512 threads, 8m x 4n per thread, f32x2, double-buffered.
// MODE 0: A = param (input), write g_xp with m=(b*T+t) -> [t][b][n]
// MODE 1: A = g_hseq (device symbol, resolved IN DEVICE CODE), write C with
//         m=(t*B+b) -> [b][t][n].
// ---------------------------------------------------------------------------
template<int KDIM, int MODE>
__global__ __launch_bounds__(512) void big_gemm(const float* __restrict__ A_param,
                                                const float* __restrict__ Bm,
                                                const float* __restrict__ bias,
                                                float* __restrict__ C) {
    // device-side resolution of the A operand (host code must NOT touch __device__ symbols)
    const float* __restrict__ A = (MODE == 1) ? g_hseq : A_param;

    __shared__ float sA[2][16][132];
    __shared__ float sB[2][16][132];
    const int m0 = blockIdx.y * 128;
    const int n0 = blockIdx.x * 128;
    const int tid = threadIdx.x;
    const int srow = tid >> 2;     // 0..127 staging row
    const int skq  = tid & 3;      // 0..3   staging k-quad
    const int tmr  = tid >> 5;     // 0..15  m-group (8 rows)
    const int tnr  = tid & 31;     // 0..31  n-group (4 cols)

    // prologue: load chunk 0 -> regs -> buf 0
    float4 ra = *reinterpret_cast<const float4*>(&A [(size_t)(m0 + srow) * KDIM + skq * 4]);
    float4 rb = *reinterpret_cast<const float4*>(&Bm[(size_t)(n0 + srow) * KDIM + skq * 4]);
    sA[0][skq * 4 + 0][srow] = ra.x; sA[0][skq * 4 + 1][srow] = ra.y;
    sA[0][skq * 4 + 2][srow] = ra.z; sA[0][skq * 4 + 3][srow] = ra.w;
    sB[0][skq * 4 + 0][srow] = rb.x; sB[0][skq * 4 + 1][srow] = rb.y;
    sB[0][skq * 4 + 2][srow] = rb.z; sB[0][skq * 4 + 3][srow] = rb.w;
    __syncthreads();

    ull acc[8][2] = {};
    const int NC = KDIM / 16;

    for (int c = 0; c < NC; c++) {
        if (c + 1 < NC) {
            ra = *reinterpret_cast<const float4*>(&A [(size_t)(m0 + srow) * KDIM + (c + 1) * 16 + skq * 4]);
            rb = *reinterpret_cast<const float4*>(&Bm[(size_t)(n0 + srow) * KDIM + (c + 1) * 16 + skq * 4]);
        }
        const int cb = c & 1;
        #pragma unroll
        for (int kk = 0; kk < 16; kk++) {
            float4 a0v = *reinterpret_cast<const float4*>(&sA[cb][kk][tmr * 8]);
            float4 a1v = *reinterpret_cast<const float4*>(&sA[cb][kk][tmr * 8 + 4]);
            ulonglong2 bv = *reinterpret_cast<const ulonglong2*>(&sB[cb][kk][tnr * 4]);
            ull a_[8];
            DUP2(a_[0], a0v.x); DUP2(a_[1], a0v.y); DUP2(a_[2], a0v.z); DUP2(a_[3], a0v.w);
            DUP2(a_[4], a1v.x); DUP2(a_[5], a1v.y); DUP2(a_[6], a1v.z); DUP2(a_[7], a1v.w);
            #pragma unroll
            for (int mi = 0; mi < 8; mi++) {
                FMA2(acc[mi][0], a_[mi], bv.x);
                FMA2(acc[mi][1], a_[mi], bv.y);
            }
        }
        if (c + 1 < NC) {
            const int nb = (c + 1) & 1;
            sA[nb][skq * 4 + 0][srow] = ra.x; sA[nb][skq * 4 + 1][srow] = ra.y;
            sA[nb][skq * 4 + 2][srow] = ra.z; sA[nb][skq * 4 + 3][srow] = ra.w;
            sB[nb][skq * 4 + 0][srow] = rb.x; sB[nb][skq * 4 + 1][srow] = rb.y;
            sB[nb][skq * 4 + 2][srow] = rb.z; sB[nb][skq * 4 + 3][srow] = rb.w;
        }
        __syncthreads();
    }

    const float4 bv4 = *reinterpret_cast<const float4*>(&bias[n0 + tnr * 4]);
    #pragma unroll
    for (int mi = 0; mi < 8; mi++) {
        const int m = m0 + tmr * 8 + mi;
        float4 v;
        UNPK2(v.x, v.y, acc[mi][0]);
        UNPK2(v.z, v.w, acc[mi][1]);
        v.x += bv4.x; v.y += bv4.y; v.z += bv4.z; v.w += bv4.w;
        if (MODE == 0) {
            const int bb = m >> 9;        // m / T_
            const int tt = m & (T_ - 1);
            *reinterpret_cast<float4*>(&g_xp[((size_t)tt * B_ + bb) * HID_ + n0 + tnr * 4]) = v;
        } else {
            const int tt = m >> 6;        // m / B_
            const int bb = m & (B_ - 1);
            *reinterpret_cast<float4*>(&C[((size_t)bb * T_ + tt) * OUT_ + n0 + tnr * 4]) = v;
        }
    }
}

// ---------------------------------------------------------------------------
// Persistent recurrence: ONE launch for all 512 steps.
// 128 blocks (jx 0..7: j-tile 128, ksi 0..15: k-slice 64), 512 threads.
// sW resident in SMEM (32KB) for the whole sequence. Per step:
//   stage shh slice (16KB, ldcg) -> sync-free GEMM -> partials (L2, ping-pong)
//   -> barrier -> disjoint reduce + tanh -> hT + hseq -> barrier.
// ---------------------------------------------------------------------------
__global__ __launch_bounds__(512, 1) void rnn_persistent(const float* __restrict__ Whh) {
    __shared__ float sW[64][128];   // [k][j] resident (32KB)
    __shared__ float sh[64][64];    // [k][b] per-step slice (16KB); sred overlays

    const int tid = threadIdx.x;
    const int bid = blockIdx.x;
    const int jx  = bid & (JT_ - 1);
    const int ksi = bid >> 3;
    const int j0  = jx * 128;
    const int k0  = ksi * 64;
    const int w    = tid >> 5;
    const int lane = tid & 31;
    // square warp footprint: 8 j-quads (128B) x 4 b-quads (64B) per warp
    const int tjq = (w & 3) * 8 + (lane & 7);    // 0..31 -> j = j0 + tjq*4
    const int tbq = (w >> 2) * 4 + (lane >> 3);  // 0..15 -> b = tbq*4
    // disjoint reduce region: 64 j x 8 b per block
    const int rj0 = (bid & 15) * 64;
    const int rb0 = (bid >> 4) * 8;
    const int rj = rj0 + (tid & 63);
    const int rb = rb0 + (tid >> 6);
    float* sred = &sh[0][0];        // overlay: 64 x 9 floats (sh dead during reduce)

    const unsigned base = ld_acq(&g_phase);
    unsigned ord = 0;

    // resident W tile: sW[k][j] <- Whh[j0+jj][k0+k]
    #pragma unroll
    for (int q = 0; q < 4; q++) {
        const int idx = q * 512 + tid;   // 2048 float4
        const int jj = idx >> 4;
        const int kq = idx & 15;
        float4 wv = *reinterpret_cast<const float4*>(&Whh[(size_t)(j0 + jj) * HID_ + k0 + kq * 4]);
        sW[kq * 4 + 0][jj] = wv.x; sW[kq * 4 + 1][jj] = wv.y;
        sW[kq * 4 + 2][jj] = wv.z; sW[kq * 4 + 3][jj] = wv.w;
    }

    // ---- step 0: h0 = tanh(xp[0]) over this block's disjoint region ----
    {
        const size_t off = (size_t)rb * HID_ + rj;
        const float v = tanhf(g_xp[off]);
        g_hseq[off] = v;
        sred[(tid & 63) * 9 + (tid >> 6)] = v;
        __syncthreads();
        const int jrow = tid >> 3, bcol = tid & 7;
        g_hT[0][(rj0 + jrow) * B_ + rb0 + bcol] = sred[jrow * 9 + bcol];
    }
    grid_barrier(base, ++ord);

    for (int t = 1; t < T_; t++) {
        const float* __restrict__ hTp = g_hT[(t - 1) & 1];

        // stage h slice: sh[k][b] <- hT[k0+k][b]
        #pragma unroll
        for (int q = 0; q < 2; q++) {
            const int idx = q * 512 + tid;   // 1024 float4
            const int k = idx >> 4;
            const int b4 = idx & 15;
            float4 hv = ldcg_f4(&hTp[(k0 + k) * B_ + b4 * 4]);
            *reinterpret_cast<float4*>(&sh[k][b4 * 4]) = hv;
        }
        __syncthreads();

        // sync-free GEMM over resident smem
        ull acc[2][4] = {};
        #pragma unroll 16
        for (int kk = 0; kk < 64; kk++) {
            ulonglong2 h2 = *reinterpret_cast<const ulonglong2*>(&sh[kk][tbq * 4]);
            float4 wv = *reinterpret_cast<const float4*>(&sW[kk][tjq * 4]);
            ull w0, w1, w2, w3;
            DUP2(w0, wv.x); DUP2(w1, wv.y); DUP2(w2, wv.z); DUP2(w3, wv.w);
            FMA2(acc[0][0], h2.x, w0); FMA2(acc[0][1], h2.x, w1);
            FMA2(acc[0][2], h2.x, w2); FMA2(acc[0][3], h2.x, w3);
            FMA2(acc[1][0], h2.y, w0); FMA2(acc[1][1], h2.y, w1);
            FMA2(acc[1][2], h2.y, w2); FMA2(acc[1][3], h2.y, w3);
        }

        // write partials (ping-pong buffer by t parity)
        {
            float* __restrict__ pdst = g_part[t & 1][ksi];
            float4 r0, r1, r2, r3;
            UNPK2(r0.x, r1.x, acc[0][0]); UNPK2(r0.y, r1.y, acc[0][1]);
            UNPK2(r0.z, r1.z, acc[0][2]); UNPK2(r0.w, r1.w, acc[0][3]);
            UNPK2(r2.x, r3.x, acc[1][0]); UNPK2(r2.y, r3.y, acc[1][1]);
            UNPK2(r2.z, r3.z, acc[1][2]); UNPK2(r2.w, r3.w, acc[1][3]);
            const size_t o = (size_t)(tbq * 4) * HID_ + j0 + tjq * 4;
            stcg_f4(&pdst[o],            r0);
            stcg_f4(&pdst[o + HID_],     r1);
            stcg_f4(&pdst[o + 2 * HID_], r2);
            stcg_f4(&pdst[o + 3 * HID_], r3);
        }

        grid_barrier(base, ++ord);   // all partials published

        // disjoint reduce + tanh; write hseq[t] and transposed hT[t&1]
        {
            const size_t off = (size_t)rb * HID_ + rj;
            float s = g_xp[(size_t)t * B_ * HID_ + off];
            #pragma unroll
            for (int ks = 0; ks < KS_; ks++)
                s += ldcg_f(&g_part[t & 1][ks][off]);
            const float v = tanhf(s);
            g_hseq[(size_t)t * B_ * HID_ + off] = v;
            sred[(tid & 63) * 9 + (tid >> 6)] = v;
            __syncthreads();
            const int jrow = tid >> 3, bcol = tid & 7;
            g_hT[t & 1][(rj0 + jrow) * B_ + rb0 + bcol] = sred[jrow * 9 + bcol];
        }

        grid_barrier(base, ++ord);   // hT[t] published
    }
}

// ---------------------------------------------------------------------------
extern "C" void kernel_launch(void* const* d_in, const int* in_sizes, int n_in,
                              void* d_out, int out_size) {
    const float* input = (const float*)d_in[0];
    const float* W_ih  = (const float*)d_in[1];
    const float* W_hh  = (const float*)d_in[2];
    const float* bias  = (const float*)d_in[3];
    const float* W_out = (const float*)d_in[4];
    const float* b_out = (const float*)d_in[5];
    float* out = (float*)d_out;

    // 1) input projection for all timesteps
    big_gemm<IN_, 0><<<dim3(HID_ / 128, (B_ * T_) / 128), 512>>>(input, W_ih, bias, nullptr);

    // 2) persistent recurrence: one kernel for all 512 steps
    rnn_persistent<<<NBLK, 512>>>(W_hh);

    // 3) output projection for all timesteps (A = g_hseq resolved in device code)
    big_gemm<HID_, 1><<<dim3(OUT_ / 128, (B_ * T_) / 128), 512>>>(nullptr, W_out, b_out, out);
}

// round 13
// speedup vs baseline: 1.1077x; 1.0632x over previous
#include <cuda_runtime.h>
#include <math.h>

// Problem dims (fixed for this dataset)
#define B_   64
#define T_   512
#define IN_  512
#define HID_ 1024
#define OUT_ 512
#define NBLK 128        // persistent blocks (<=148 SMs -> all co-resident)
#define KS_  16         // split-K slices (64 k each)
#define JT_  8          // j-tiles of 128

typedef unsigned long long ull;

// packed fp32x2 FMA helpers (bit-identical to scalar FFMA)
#define FMA2(d, a, b) asm("fma.rn.f32x2 %0, %1, %2, %0;" : "+l"(d) : "l"(a), "l"(b))
#define DUP2(d, s)    asm("mov.b64 %0, {%1, %1};" : "=l"(d) : "r"(__float_as_uint(s)))
#define UNPK2(lo, hi, s) asm("mov.b64 {%0, %1}, %2;" : "=f"(lo), "=f"(hi) : "l"(s))

// Scratch (allocation-free contract: __device__ globals; BSS zero-init)
__device__ float g_xp[(size_t)T_ * B_ * HID_];     // [t][b][j]
__device__ float g_hseq[(size_t)T_ * B_ * HID_];   // [t][b][j]
__device__ float g_hT[2][HID_ * B_];               // ping-pong transposed hidden [j][b]
__device__ float g_part[2][KS_][B_ * HID_];        // double-buffered split-K partials
__device__ unsigned g_flags[NBLK];                 // per-block arrival flags (monotonic)
__device__ unsigned g_phase;                       // release word (monotonic)

__device__ __forceinline__ float ldcg_f(const float* p) {
    float v; asm volatile("ld.global.cg.f32 %0, [%1];" : "=f"(v) : "l"(p)); return v;
}
__device__ __forceinline__ float4 ldcg_f4(const float* p) {
    float4 v;
    asm volatile("ld.global.cg.v4.f32 {%0,%1,%2,%3}, [%4];"
                 : "=f"(v.x), "=f"(v.y), "=f"(v.z), "=f"(v.w) : "l"(p));
    return v;
}
__device__ __forceinline__ void stcg_f4(float* p, float4 v) {
    asm volatile("st.global.cg.v4.f32 [%0], {%1,%2,%3,%4};"
                 :: "l"(p), "f"(v.x), "f"(v.y), "f"(v.z), "f"(v.w));
}
__device__ __forceinline__ unsigned ld_acq(const unsigned* p) {
    unsigned v; asm volatile("ld.acquire.gpu.u32 %0, [%1];" : "=r"(v) : "l"(p)); return v;
}
__device__ __forceinline__ void st_rel(unsigned* p, unsigned v) {
    asm volatile("st.release.gpu.u32 [%0], %1;" :: "l"(p), "r"(v));
}

// Flag-array grid barrier: no contended atomics. Block 0 collects all flags,
// bumps the phase word. Values are monotonic (base + ord) -> graph-replay-safe,
// nothing to reset. Acquire/release on the signal words.
__device__ __forceinline__ void grid_barrier(unsigned base, unsigned ord) {
    const unsigned tgt = base + ord;
    const int tid = threadIdx.x;
    __threadfence();       // publish this block's data writes
    __syncthreads();
    if (blockIdx.x == 0) {
        if (tid >= 1 && tid < NBLK) {
            while ((int)(ld_acq(&g_flags[tid]) - tgt) < 0) __nanosleep(32);
        }
        __syncthreads();
        if (tid == 0) st_rel(&g_phase, tgt);
    } else {
        if (tid == 0) {
            st_rel(&g_flags[blockIdx.x], tgt);
            while ((int)(ld_acq(&g_phase) - tgt) < 0) __nanosleep(32);
        }
        __syncthreads();
    }
    __threadfence();
}

// ---------------------------------------------------------------------------
// Big GEMM (both projections): C[m,n] = sum_k A[m,k]*Bm[n,k] + bias[n]
// 128x128 block tile, 512 threads, 8m x 4n per thread, f32x2, double-buffered.
// MODE 0: A = param (input), write g_xp with m=(b*T+t) -> [t][b][n]
// MODE 1: A = g_hseq (device symbol, resolved IN DEVICE CODE), write C with
//         m=(t*B+b) -> [b][t][n].
// ---------------------------------------------------------------------------
template<int KDIM, int MODE>
__global__ __launch_bounds__(512) void big_gemm(const float* __restrict__ A_param,
                                                const float* __restrict__ Bm,
                                                const float* __restrict__ bias,
                                                float* __restrict__ C) {
    // device-side resolution of the A operand (host code must NOT touch __device__ symbols)
    const float* __restrict__ A = (MODE == 1) ? g_hseq : A_param;

    __shared__ float sA[2][16][132];
    __shared__ float sB[2][16][132];
    const int m0 = blockIdx.y * 128;
    const int n0 = blockIdx.x * 128;
    const int tid = threadIdx.x;
    const int srow = tid >> 2;     // 0..127 staging row
    const int skq  = tid & 3;      // 0..3   staging k-quad
    const int tmr  = tid >> 5;     // 0..15  m-group (8 rows)
    const int tnr  = tid & 31;     // 0..31  n-group (4 cols)

    // prologue: load chunk 0 -> regs -> buf 0
    float4 ra = *reinterpret_cast<const float4*>(&A [(size_t)(m0 + srow) * KDIM + skq * 4]);
    float4 rb = *reinterpret_cast<const float4*>(&Bm[(size_t)(n0 + srow) * KDIM + skq * 4]);
    sA[0][skq * 4 + 0][srow] = ra.x; sA[0][skq * 4 + 1][srow] = ra.y;
    sA[0][skq * 4 + 2][srow] = ra.z; sA[0][skq * 4 + 3][srow] = ra.w;
    sB[0][skq * 4 + 0][srow] = rb.x; sB[0][skq * 4 + 1][srow] = rb.y;
    sB[0][skq * 4 + 2][srow] = rb.z; sB[0][skq * 4 + 3][srow] = rb.w;
    __syncthreads();

    ull acc[8][2] = {};
    const int NC = KDIM / 16;

    for (int c = 0; c < NC; c++) {
        if (c + 1 < NC) {
            ra = *reinterpret_cast<const float4*>(&A [(size_t)(m0 + srow) * KDIM + (c + 1) * 16 + skq * 4]);
            rb = *reinterpret_cast<const float4*>(&Bm[(size_t)(n0 + srow) * KDIM + (c + 1) * 16 + skq * 4]);
        }
        const int cb = c & 1;
        #pragma unroll
        for (int kk = 0; kk < 16; kk++) {
            float4 a0v = *reinterpret_cast<const float4*>(&sA[cb][kk][tmr * 8]);
            float4 a1v = *reinterpret_cast<const float4*>(&sA[cb][kk][tmr * 8 + 4]);
            ulonglong2 bv = *reinterpret_cast<const ulonglong2*>(&sB[cb][kk][tnr * 4]);
            ull a_[8];
            DUP2(a_[0], a0v.x); DUP2(a_[1], a0v.y); DUP2(a_[2], a0v.z); DUP2(a_[3], a0v.w);
            DUP2(a_[4], a1v.x); DUP2(a_[5], a1v.y); DUP2(a_[6], a1v.z); DUP2(a_[7], a1v.w);
            #pragma unroll
            for (int mi = 0; mi < 8; mi++) {
                FMA2(acc[mi][0], a_[mi], bv.x);
                FMA2(acc[mi][1], a_[mi], bv.y);
            }
        }
        if (c + 1 < NC) {
            const int nb = (c + 1) & 1;
            sA[nb][skq * 4 + 0][srow] = ra.x; sA[nb][skq * 4 + 1][srow] = ra.y;
            sA[nb][skq * 4 + 2][srow] = ra.z; sA[nb][skq * 4 + 3][srow] = ra.w;
            sB[nb][skq * 4 + 0][srow] = rb.x; sB[nb][skq * 4 + 1][srow] = rb.y;
            sB[nb][skq * 4 + 2][srow] = rb.z; sB[nb][skq * 4 + 3][srow] = rb.w;
        }
        __syncthreads();
    }

    const float4 bv4 = *reinterpret_cast<const float4*>(&bias[n0 + tnr * 4]);
    #pragma unroll
    for (int mi = 0; mi < 8; mi++) {
        const int m = m0 + tmr * 8 + mi;
        float4 v;
        UNPK2(v.x, v.y, acc[mi][0]);
        UNPK2(v.z, v.w, acc[mi][1]);
        v.x += bv4.x; v.y += bv4.y; v.z += bv4.z; v.w += bv4.w;
        if (MODE == 0) {
            const int bb = m >> 9;        // m / T_
            const int tt = m & (T_ - 1);
            *reinterpret_cast<float4*>(&g_xp[((size_t)tt * B_ + bb) * HID_ + n0 + tnr * 4]) = v;
        } else {
            const int tt = m >> 6;        // m / B_
            const int bb = m & (B_ - 1);
            *reinterpret_cast<float4*>(&C[((size_t)bb * T_ + tt) * OUT_ + n0 + tnr * 4]) = v;
        }
    }
}

// ---------------------------------------------------------------------------
// Persistent recurrence: ONE launch for all 512 steps.
// 128 blocks (jx 0..7: j-tile 128, ksi 0..15: k-slice 64), 512 threads.
// sW resident in SMEM (32KB) for the whole sequence. Per step:
//   stage shh slice (16KB, ldcg) -> sync-free GEMM -> partials (L2, ping-pong)
//   -> barrier -> disjoint reduce + tanh -> hT + hseq -> barrier.
// ---------------------------------------------------------------------------
__global__ __launch_bounds__(512, 1) void rnn_persistent(const float* __restrict__ Whh) {
    __shared__ float sW[64][128];   // [k][j] resident (32KB)
    __shared__ float sh[64][64];    // [k][b] per-step slice (16KB); sred overlays

    const int tid = threadIdx.x;
    const int bid = blockIdx.x;
    const int jx  = bid & (JT_ - 1);
    const int ksi = bid >> 3;
    const int j0  = jx * 128;
    const int k0  = ksi * 64;
    const int w    = tid >> 5;
    const int lane = tid & 31;
    // square warp footprint: 8 j-quads (128B) x 4 b-quads (64B) per warp
    const int tjq = (w & 3) * 8 + (lane & 7);    // 0..31 -> j = j0 + tjq*4
    const int tbq = (w >> 2) * 4 + (lane >> 3);  // 0..15 -> b = tbq*4
    // disjoint reduce region: 64 j x 8 b per block
    const int rj0 = (bid & 15) * 64;
    const int rb0 = (bid >> 4) * 8;
    const int rj = rj0 + (tid & 63);
    const int rb = rb0 + (tid >> 6);
    float* sred = &sh[0][0];        // overlay: 64 x 9 floats (sh dead during reduce)

    const unsigned base = ld_acq(&g_phase);
    unsigned ord = 0;

    // resident W tile: sW[k][j] <- Whh[j0+jj][k0+k]
    #pragma unroll
    for (int q = 0; q < 4; q++) {
        const int idx = q * 512 + tid;   // 2048 float4
        const int jj = idx >> 4;
        const int kq = idx & 15;
        float4 wv = *reinterpret_cast<const float4*>(&Whh[(size_t)(j0 + jj) * HID_ + k0 + kq * 4]);
        sW[kq * 4 + 0][jj] = wv.x; sW[kq * 4 + 1][jj] = wv.y;
        sW[kq * 4 + 2][jj] = wv.z; sW[kq * 4 + 3][jj] = wv.w;
    }

    // ---- step 0: h0 = tanh(xp[0]) over this block's disjoint region ----
    {
        const size_t off = (size_t)rb * HID_ + rj;
        const float v = tanhf(g_xp[off]);
        g_hseq[off] = v;
        sred[(tid & 63) * 9 + (tid >> 6)] = v;
        __syncthreads();
        const int jrow = tid >> 3, bcol = tid & 7;
        g_hT[0][(rj0 + jrow) * B_ + rb0 + bcol] = sred[jrow * 9 + bcol];
    }
    grid_barrier(base, ++ord);

    for (int t = 1; t < T_; t++) {
        const float* __restrict__ hTp = g_hT[(t - 1) & 1];

        // stage h slice: sh[k][b] <- hT[k0+k][b]
        #pragma unroll
        for (int q = 0; q < 2; q++) {
            const int idx = q * 512 + tid;   // 1024 float4
            const int k = idx >> 4;
            const int b4 = idx & 15;
            float4 hv = ldcg_f4(&hTp[(k0 + k) * B_ + b4 * 4]);
            *reinterpret_cast<float4*>(&sh[k][b4 * 4]) = hv;
        }
        __syncthreads();

        // sync-free GEMM over resident smem
        ull acc[2][4] = {};
        #pragma unroll 16
        for (int kk = 0; kk < 64; kk++) {
            ulonglong2 h2 = *reinterpret_cast<const ulonglong2*>(&sh[kk][tbq * 4]);
            float4 wv = *reinterpret_cast<const float4*>(&sW[kk][tjq * 4]);
            ull w0, w1, w2, w3;
            DUP2(w0, wv.x); DUP2(w1, wv.y); DUP2(w2, wv.z); DUP2(w3, wv.w);
            FMA2(acc[0][0], h2.x, w0); FMA2(acc[0][1], h2.x, w1);
            FMA2(acc[0][2], h2.x, w2); FMA2(acc[0][3], h2.x, w3);
            FMA2(acc[1][0], h2.y, w0); FMA2(acc[1][1], h2.y, w1);
            FMA2(acc[1][2], h2.y, w2); FMA2(acc[1][3], h2.y, w3);
        }

        // write partials (ping-pong buffer by t parity)
        {
            float* __restrict__ pdst = g_part[t & 1][ksi];
            float4 r0, r1, r2, r3;
            UNPK2(r0.x, r1.x, acc[0][0]); UNPK2(r0.y, r1.y, acc[0][1]);
            UNPK2(r0.z, r1.z, acc[0][2]); UNPK2(r0.w, r1.w, acc[0][3]);
            UNPK2(r2.x, r3.x, acc[1][0]); UNPK2(r2.y, r3.y, acc[1][1]);
            UNPK2(r2.z, r3.z, acc[1][2]); UNPK2(r2.w, r3.w, acc[1][3]);
            const size_t o = (size_t)(tbq * 4) * HID_ + j0 + tjq * 4;
            stcg_f4(&pdst[o],            r0);
            stcg_f4(&pdst[o + HID_],     r1);
            stcg_f4(&pdst[o + 2 * HID_], r2);
            stcg_f4(&pdst[o + 3 * HID_], r3);
        }

        grid_barrier(base, ++ord);   // all partials published

        // disjoint reduce + tanh; write hseq[t] and transposed hT[t&1]
        {
            const size_t off = (size_t)rb * HID_ + rj;
            float s = g_xp[(size_t)t * B_ * HID_ + off];
            #pragma unroll
            for (int ks = 0; ks < KS_; ks++)
                s += ldcg_f(&g_part[t & 1][ks][off]);
            const float v = tanhf(s);
            g_hseq[(size_t)t * B_ * HID_ + off] = v;
            sred[(tid & 63) * 9 + (tid >> 6)] = v;
            __syncthreads();
            const int jrow = tid >> 3, bcol = tid & 7;
            g_hT[t & 1][(rj0 + jrow) * B_ + rb0 + bcol] = sred[jrow * 9 + bcol];
        }

        grid_barrier(base, ++ord);   // hT[t] published
    }
}

// ---------------------------------------------------------------------------
extern "C" void kernel_launch(void* const* d_in, const int* in_sizes, int n_in,
                              void* d_out, int out_size) {
    const float* input = (const float*)d_in[0];
    const float* W_ih  = (const float*)d_in[1];
    const float* W_hh  = (const float*)d_in[2];
    const float* bias  = (const float*)d_in[3];
    const float* W_out = (const float*)d_in[4];
    const float* b_out = (const float*)d_in[5];
    float* out = (float*)d_out;

    // 1) input projection for all timesteps
    big_gemm<IN_, 0><<<dim3(HID_ / 128, (B_ * T_) / 128), 512>>>(input, W_ih, bias, nullptr);

    // 2) persistent recurrence: one kernel for all 512 steps
    rnn_persistent<<<NBLK, 512>>>(W_hh);

    // 3) output projection for all timesteps (A = g_hseq resolved in device code)
    big_gemm<HID_, 1><<<dim3(OUT_ / 128, (B_ * T_) / 128), 512>>>(nullptr, W_out, b_out, out);
}